// round 6
// baseline (speedup 1.0000x reference)
#include <cuda_runtime.h>
#include <math.h>

#define BATCH 2
#define SEQ 2048
#define DMODEL 1024
#define NHEADS 16
#define DKDIM 64
#define MROWS (BATCH*SEQ)      // 4096
#define NQKV (3*DMODEL)        // 3072

// Scratch (device globals -- no allocation in kernel_launch)
__device__ float g_q[(size_t)BATCH*NHEADS*SEQ*DKDIM];
__device__ float g_k[(size_t)BATCH*NHEADS*SEQ*DKDIM];
__device__ float g_v[(size_t)BATCH*NHEADS*SEQ*DKDIM];
__device__ float g_attn[(size_t)MROWS*DMODEL];
__device__ float2 g_rope[(size_t)SEQ*32];   // (cos,sin) per (s, d/2)

// ---------------------------------------------------------------------------
// Kernel 0: RoPE cos/sin table  (2048 x 32 float2 = 512 KB, L2 resident)
// ---------------------------------------------------------------------------
__global__ void rope_table_kernel(const int* __restrict__ tokpos)
{
    int i = blockIdx.x * blockDim.x + threadIdx.x;   // 0..65535
    int s  = i >> 5;
    int d2 = i & 31;
    float pos  = (float)tokpos[s];
    float freq = powf(10000.0f, -(float)(2*d2) * (1.0f/64.0f));
    float sn, cs;
    sincosf(pos * freq, &sn, &cs);
    g_rope[i] = make_float2(cs, sn);
}

// ---------------------------------------------------------------------------
// GEMM tiling: 128x128 tile, BK=16, 256 threads, 8x8 micro-tile,
// register-staged global prefetch.
// ---------------------------------------------------------------------------
#define GBM 128
#define GBN 128
#define GBK 16

// Kernel 1: QKV GEMM (C = x * Wqkv^T) + fused RoPE scatter to [B,H,S,DK]
__global__ __launch_bounds__(256)
void qkv_gemm_kernel(const float* __restrict__ x,
                     const float* __restrict__ Wqkv)
{
    __shared__ float As[GBK][GBM + 4];
    __shared__ float Bs[GBK][GBN + 4];

    const int tid  = threadIdx.x;
    const int tx   = tid & 15;
    const int ty   = tid >> 4;
    const int row0 = blockIdx.x * GBM;
    const int col0 = blockIdx.y * GBN;
    const int lr   = tid >> 2;          // 0..63
    const int lk   = (tid & 3) * 4;     // 0,4,8,12

    const float* ap = x    + (size_t)(row0 + lr) * DMODEL + lk;
    const float* bp = Wqkv + (size_t)(col0 + lr) * DMODEL + lk;

    float4 pa0 = *(const float4*)(ap);
    float4 pa1 = *(const float4*)(ap + (size_t)64 * DMODEL);
    float4 pb0 = *(const float4*)(bp);
    float4 pb1 = *(const float4*)(bp + (size_t)64 * DMODEL);

    float c[8][8];
    #pragma unroll
    for (int i = 0; i < 8; i++)
        #pragma unroll
        for (int j = 0; j < 8; j++) c[i][j] = 0.f;

    for (int k0 = 0; k0 < DMODEL; k0 += GBK) {
        As[lk+0][lr]    = pa0.x; As[lk+1][lr]    = pa0.y; As[lk+2][lr]    = pa0.z; As[lk+3][lr]    = pa0.w;
        As[lk+0][lr+64] = pa1.x; As[lk+1][lr+64] = pa1.y; As[lk+2][lr+64] = pa1.z; As[lk+3][lr+64] = pa1.w;
        Bs[lk+0][lr]    = pb0.x; Bs[lk+1][lr]    = pb0.y; Bs[lk+2][lr]    = pb0.z; Bs[lk+3][lr]    = pb0.w;
        Bs[lk+0][lr+64] = pb1.x; Bs[lk+1][lr+64] = pb1.y; Bs[lk+2][lr+64] = pb1.z; Bs[lk+3][lr+64] = pb1.w;
        __syncthreads();

        if (k0 + GBK < DMODEL) {
            pa0 = *(const float4*)(ap + k0 + GBK);
            pa1 = *(const float4*)(ap + (size_t)64 * DMODEL + k0 + GBK);
            pb0 = *(const float4*)(bp + k0 + GBK);
            pb1 = *(const float4*)(bp + (size_t)64 * DMODEL + k0 + GBK);
        }

        #pragma unroll
        for (int kk = 0; kk < GBK; kk++) {
            float4 a0 = *(const float4*)&As[kk][ty*4];
            float4 a1 = *(const float4*)&As[kk][ty*4 + 64];
            float4 b0 = *(const float4*)&Bs[kk][tx*4];
            float4 b1 = *(const float4*)&Bs[kk][tx*4 + 64];
            float a[8] = {a0.x,a0.y,a0.z,a0.w, a1.x,a1.y,a1.z,a1.w};
            float b[8] = {b0.x,b0.y,b0.z,b0.w, b1.x,b1.y,b1.z,b1.w};
            #pragma unroll
            for (int i = 0; i < 8; i++)
                #pragma unroll
                for (int j = 0; j < 8; j++)
                    c[i][j] += a[i] * b[j];
        }
        __syncthreads();
    }

    // Epilogue: RoPE (q,k) via table, plain scatter (v).
    #pragma unroll
    for (int i = 0; i < 8; i++) {
        const int r = ty*4 + (i & 3) + (i >> 2) * 64;
        const int m = row0 + r;
        const int b = m >> 11;        // /SEQ (2048)
        const int s = m & 2047;
        #pragma unroll
        for (int jg = 0; jg < 8; jg += 2) {
            const int col    = col0 + tx*4 + (jg & 3) + (jg >> 2) * 64;
            const int which  = col >> 10;          // 0=q 1=k 2=v
            const int within = col & 1023;
            const int h      = within >> 6;
            const int d      = within & 63;        // even
            const float e0 = c[i][jg];
            const float e1 = c[i][jg+1];
            float* base = (which == 0) ? g_q : (which == 1) ? g_k : g_v;
            float* dst  = base + ((size_t)(b*NHEADS + h)*SEQ + s)*DKDIM + d;
            if (which == 2) {
                *(float2*)dst = make_float2(e0, e1);
            } else {
                const float2 cssn = g_rope[(s << 5) + (d >> 1)];
                *(float2*)dst = make_float2(e0*cssn.x - e1*cssn.y,
                                            e0*cssn.y + e1*cssn.x);
            }
        }
    }
}

// ---------------------------------------------------------------------------
// Kernel 2: causal flash attention, fp32.
// 128 threads/block, one query row per thread; q & acc in registers.
// Key tiles of 32 rows; scores staged in padded SMEM.
// ---------------------------------------------------------------------------
#define FBM 128
#define FBN 32

__global__ __launch_bounds__(128)
void attn_kernel()
{
    __shared__ float Ksh[FBN][DKDIM];        // 8 KB
    __shared__ float Vsh[FBN][DKDIM];        // 8 KB
    __shared__ float Ssh[FBM][FBN + 1];      // 16.5 KB, stride 33 -> conflict free

    const int tid = threadIdx.x;
    const int qb  = (int)gridDim.x - 1 - (int)blockIdx.x;   // heavy blocks first
    const int bh  = blockIdx.y;
    const int qi  = qb*FBM + tid;

    const float* qptr = g_q + ((size_t)bh*SEQ + qi)*DKDIM;
    float4 qr[16];
    #pragma unroll
    for (int i = 0; i < 16; i++) {
        qr[i] = *(const float4*)(qptr + i*4);
        qr[i].x *= 0.125f; qr[i].y *= 0.125f; qr[i].z *= 0.125f; qr[i].w *= 0.125f;
    }

    float4 acc[16];
    #pragma unroll
    for (int i = 0; i < 16; i++) acc[i] = make_float4(0.f, 0.f, 0.f, 0.f);
    float mrow = -1e30f, lrow = 0.f;

    const float* kb = g_k + (size_t)bh*SEQ*DKDIM;
    const float* vb = g_v + (size_t)bh*SEQ*DKDIM;
    const int nkt = (qb + 1) * (FBM / FBN);      // causal: 4*(qb+1) key tiles

    for (int kt = 0; kt < nkt; kt++) {
        const int kbase = kt * FBN;
        __syncthreads();
        const float4* kp = (const float4*)(kb + (size_t)kbase*DKDIM);
        const float4* vp = (const float4*)(vb + (size_t)kbase*DKDIM);
        #pragma unroll
        for (int i = 0; i < 4; i++) {            // 512 float4 each / 128 thr
            int idx = tid + i*128;
            ((float4*)Ksh)[idx] = kp[idx];
            ((float4*)Vsh)[idx] = vp[idx];
        }
        __syncthreads();

        // Score pass: 4 independent FMA chains per dot product.
        float tmax = -1e30f;
        #pragma unroll
        for (int j = 0; j < FBN; j++) {
            float s0 = 0.f, s1 = 0.f, s2 = 0.f, s3 = 0.f;
            #pragma unroll
            for (int dc = 0; dc < 16; dc += 4) {
                float4 k0 = *(const float4*)&Ksh[j][dc*4];
                float4 k1 = *(const float4*)&Ksh[j][dc*4 + 4];
                float4 k2 = *(const float4*)&Ksh[j][dc*4 + 8];
                float4 k3 = *(const float4*)&Ksh[j][dc*4 + 12];
                s0 += qr[dc+0].x*k0.x + qr[dc+0].y*k0.y + qr[dc+0].z*k0.z + qr[dc+0].w*k0.w;
                s1 += qr[dc+1].x*k1.x + qr[dc+1].y*k1.y + qr[dc+1].z*k1.z + qr[dc+1].w*k1.w;
                s2 += qr[dc+2].x*k2.x + qr[dc+2].y*k2.y + qr[dc+2].z*k2.z + qr[dc+2].w*k2.w;
                s3 += qr[dc+3].x*k3.x + qr[dc+3].y*k3.y + qr[dc+3].z*k3.z + qr[dc+3].w*k3.w;
            }
            float sc = (s0 + s1) + (s2 + s3);
            if (kbase + j > qi) sc = -1e30f;     // causal mask
            Ssh[tid][j] = sc;
            tmax = fmaxf(tmax, sc);
        }

        const float newm = fmaxf(mrow, tmax);
        const float corr = __expf(mrow - newm);
        mrow = newm;
        lrow *= corr;
        #pragma unroll
        for (int i = 0; i < 16; i++) {
            acc[i].x *= corr; acc[i].y *= corr; acc[i].z *= corr; acc[i].w *= corr;
        }

        #pragma unroll
        for (int j = 0; j < FBN; j++) {
            const float p = __expf(Ssh[tid][j] - newm);
            lrow += p;
            #pragma unroll
            for (int dc = 0; dc < 16; dc++) {
                float4 v4 = *(const float4*)&Vsh[j][dc*4];
                acc[dc].x += p*v4.x; acc[dc].y += p*v4.y;
                acc[dc].z += p*v4.z; acc[dc].w += p*v4.w;
            }
        }
    }

    const float inv = 1.0f / lrow;
    const int b = bh >> 4, h = bh & 15;
    float* dst = g_attn + ((size_t)(b*SEQ + qi))*DMODEL + h*DKDIM;
    #pragma unroll
    for (int dc = 0; dc < 16; dc++) {
        *(float4*)(dst + dc*4) = make_float4(acc[dc].x*inv, acc[dc].y*inv,
                                             acc[dc].z*inv, acc[dc].w*inv);
    }
}

// ---------------------------------------------------------------------------
// Kernel 3: output GEMM (out = attn * Wout^T), same 128x128x16 tiling.
// ---------------------------------------------------------------------------
__global__ __launch_bounds__(256)
void out_gemm_kernel(const float* __restrict__ Wout, float* __restrict__ out)
{
    __shared__ float As[GBK][GBM + 4];
    __shared__ float Bs[GBK][GBN + 4];

    const int tid  = threadIdx.x;
    const int tx   = tid & 15;
    const int ty   = tid >> 4;
    const int row0 = blockIdx.x * GBM;
    const int col0 = blockIdx.y * GBN;
    const int lr   = tid >> 2;
    const int lk   = (tid & 3) * 4;

    const float* ap = g_attn + (size_t)(row0 + lr) * DMODEL + lk;
    const float* bp = Wout   + (size_t)(col0 + lr) * DMODEL + lk;

    float4 pa0 = *(const float4*)(ap);
    float4 pa1 = *(const float4*)(ap + (size_t)64 * DMODEL);
    float4 pb0 = *(const float4*)(bp);
    float4 pb1 = *(const float4*)(bp + (size_t)64 * DMODEL);

    float c[8][8];
    #pragma unroll
    for (int i = 0; i < 8; i++)
        #pragma unroll
        for (int j = 0; j < 8; j++) c[i][j] = 0.f;

    for (int k0 = 0; k0 < DMODEL; k0 += GBK) {
        As[lk+0][lr]    = pa0.x; As[lk+1][lr]    = pa0.y; As[lk+2][lr]    = pa0.z; As[lk+3][lr]    = pa0.w;
        As[lk+0][lr+64] = pa1.x; As[lk+1][lr+64] = pa1.y; As[lk+2][lr+64] = pa1.z; As[lk+3][lr+64] = pa1.w;
        Bs[lk+0][lr]    = pb0.x; Bs[lk+1][lr]    = pb0.y; Bs[lk+2][lr]    = pb0.z; Bs[lk+3][lr]    = pb0.w;
        Bs[lk+0][lr+64] = pb1.x; Bs[lk+1][lr+64] = pb1.y; Bs[lk+2][lr+64] = pb1.z; Bs[lk+3][lr+64] = pb1.w;
        __syncthreads();

        if (k0 + GBK < DMODEL) {
            pa0 = *(const float4*)(ap + k0 + GBK);
            pa1 = *(const float4*)(ap + (size_t)64 * DMODEL + k0 + GBK);
            pb0 = *(const float4*)(bp + k0 + GBK);
            pb1 = *(const float4*)(bp + (size_t)64 * DMODEL + k0 + GBK);
        }

        #pragma unroll
        for (int kk = 0; kk < GBK; kk++) {
            float4 a0 = *(const float4*)&As[kk][ty*4];
            float4 a1 = *(const float4*)&As[kk][ty*4 + 64];
            float4 b0 = *(const float4*)&Bs[kk][tx*4];
            float4 b1 = *(const float4*)&Bs[kk][tx*4 + 64];
            float a[8] = {a0.x,a0.y,a0.z,a0.w, a1.x,a1.y,a1.z,a1.w};
            float b[8] = {b0.x,b0.y,b0.z,b0.w, b1.x,b1.y,b1.z,b1.w};
            #pragma unroll
            for (int i = 0; i < 8; i++)
                #pragma unroll
                for (int j = 0; j < 8; j++)
                    c[i][j] += a[i] * b[j];
        }
        __syncthreads();
    }

    #pragma unroll
    for (int i = 0; i < 8; i++) {
        const int r = ty*4 + (i & 3) + (i >> 2) * 64;
        const int m = row0 + r;
        *(float4*)(out + (size_t)m*DMODEL + col0 + tx*4)      = make_float4(c[i][0], c[i][1], c[i][2], c[i][3]);
        *(float4*)(out + (size_t)m*DMODEL + col0 + tx*4 + 64) = make_float4(c[i][4], c[i][5], c[i][6], c[i][7]);
    }
}

// ---------------------------------------------------------------------------
extern "C" void kernel_launch(void* const* d_in, const int* in_sizes, int n_in,
                              void* d_out, int out_size)
{
    const float* x      = (const float*)d_in[0];
    const int*   tokpos = (const int*)  d_in[1];
    const float* Wqkv   = (const float*)d_in[2];
    const float* Wout   = (const float*)d_in[3];
    float*       out    = (float*)d_out;

    rope_table_kernel<<<SEQ*32/256, 256>>>(tokpos);
    qkv_gemm_kernel<<<dim3(MROWS/GBM, NQKV/GBN), 256>>>(x, Wqkv);
    attn_kernel<<<dim3(SEQ/FBM, BATCH*NHEADS), 128>>>();
    out_gemm_kernel<<<dim3(MROWS/GBM, DMODEL/GBN), 256>>>(Wout, out);
}

// round 7
// speedup vs baseline: 1.7727x; 1.7727x over previous
#include <cuda_runtime.h>
#include <math.h>

#define BATCH 2
#define SEQ 2048
#define DMODEL 1024
#define NHEADS 16
#define DKDIM 64
#define MROWS (BATCH*SEQ)      // 4096
#define NQKV (3*DMODEL)        // 3072

// Scratch (device globals -- no allocation in kernel_launch)
__device__ float g_q[(size_t)BATCH*NHEADS*SEQ*DKDIM];
__device__ float g_k[(size_t)BATCH*NHEADS*SEQ*DKDIM];
__device__ float g_v[(size_t)BATCH*NHEADS*SEQ*DKDIM];
__device__ float g_attn[(size_t)MROWS*DMODEL];
__device__ float2 g_rope[(size_t)SEQ*32];   // (cos,sin) per (s, d/2)

// ---------------------------------------------------------------------------
// Kernel 0: RoPE cos/sin table (2048 x 32 float2 = 512 KB)
// ---------------------------------------------------------------------------
__global__ void rope_table_kernel(const int* __restrict__ tokpos)
{
    int i  = blockIdx.x * blockDim.x + threadIdx.x;
    int s  = i >> 5;
    int d2 = i & 31;
    float pos  = (float)tokpos[s];
    float freq = powf(10000.0f, -(float)(2*d2) * (1.0f/64.0f));
    float sn, cs;
    sincosf(pos * freq, &sn, &cs);
    g_rope[i] = make_float2(cs, sn);
}

// ---------------------------------------------------------------------------
// GEMM tiling (REVERTED to measured-good 64x64x16, 256 thr, 4x4 micro-tile)
// ---------------------------------------------------------------------------
#define BM 64
#define BN 64
#define BK 16

// Kernel 1: QKV GEMM (C = x * Wqkv^T) + fused RoPE scatter
__global__ __launch_bounds__(256)
void qkv_gemm_kernel(const float* __restrict__ x,
                     const float* __restrict__ Wqkv)
{
    __shared__ float As[BK][BM + 4];
    __shared__ float Bs[BK][BN + 4];

    const int tid  = threadIdx.x;
    const int row0 = blockIdx.x * BM;
    const int col0 = blockIdx.y * BN;
    const int tx = tid & 15;
    const int ty = tid >> 4;
    const int lr = tid >> 2;
    const int lk = (tid & 3) * 4;

    float c[4][4] = {};

    for (int k0 = 0; k0 < DMODEL; k0 += BK) {
        float4 a4 = *(const float4*)(x    + (size_t)(row0 + lr) * DMODEL + k0 + lk);
        float4 b4 = *(const float4*)(Wqkv + (size_t)(col0 + lr) * DMODEL + k0 + lk);
        __syncthreads();
        As[lk+0][lr] = a4.x; As[lk+1][lr] = a4.y; As[lk+2][lr] = a4.z; As[lk+3][lr] = a4.w;
        Bs[lk+0][lr] = b4.x; Bs[lk+1][lr] = b4.y; Bs[lk+2][lr] = b4.z; Bs[lk+3][lr] = b4.w;
        __syncthreads();
        #pragma unroll
        for (int kk = 0; kk < BK; kk++) {
            float4 av = *(const float4*)&As[kk][ty*4];
            float4 bv = *(const float4*)&Bs[kk][tx*4];
            float a[4] = {av.x, av.y, av.z, av.w};
            float b[4] = {bv.x, bv.y, bv.z, bv.w};
            #pragma unroll
            for (int i = 0; i < 4; i++)
                #pragma unroll
                for (int j = 0; j < 4; j++)
                    c[i][j] += a[i] * b[j];
        }
    }

    #pragma unroll
    for (int i = 0; i < 4; i++) {
        const int m = row0 + ty*4 + i;
        const int b = m >> 11;
        const int s = m & 2047;
        #pragma unroll
        for (int jj = 0; jj < 4; jj += 2) {
            const int o      = col0 + tx*4 + jj;
            const int which  = o >> 10;          // 0=q 1=k 2=v
            const int within = o & 1023;
            const int h      = within >> 6;
            const int d      = within & 63;      // even
            const float e0 = c[i][jj];
            const float e1 = c[i][jj+1];
            float* base = (which == 0) ? g_q : (which == 1) ? g_k : g_v;
            float* dst  = base + ((size_t)(b*NHEADS + h)*SEQ + s)*DKDIM + d;
            if (which == 2) {
                *(float2*)dst = make_float2(e0, e1);
            } else {
                const float2 cssn = g_rope[(s << 5) + (d >> 1)];
                *(float2*)dst = make_float2(e0*cssn.x - e1*cssn.y,
                                            e0*cssn.y + e1*cssn.x);
            }
        }
    }
}

// ---------------------------------------------------------------------------
// Kernel 2: causal flash attention as two SMEM GEMMs.
// 256 threads, 128 queries/block, 32-key tiles.
// Score phase: 4x4 micro-tile (sx=tid&7 over 32 cols, sy=tid>>3 over 128 rows)
// PV phase:    4x8 micro-tile (same sy rows, sx over 64 dims)
// ---------------------------------------------------------------------------
#define ABM 128
#define ABN 32

__global__ __launch_bounds__(256)
void attn_kernel()
{
    __shared__ float Qt[DKDIM][ABM + 4];   // Q^T, scaled       33.8 KB
    __shared__ float Kt[DKDIM][36];        // K^T tile           9.2 KB
    __shared__ float Pt[ABN][ABM + 4];     // P^T tile          16.9 KB
    __shared__ float Vsh[ABN][DKDIM];      // V tile             8.0 KB
    __shared__ float m_row[ABM];
    __shared__ float l_row[ABM];

    const int tid = threadIdx.x;
    const int qb  = (SEQ/ABM - 1) - (int)blockIdx.x;   // heavy blocks first
    const int bh  = blockIdx.y;
    const int q0  = qb * ABM;
    const int sx  = tid & 7;
    const int sy  = tid >> 3;          // 0..31, owns rows sy*4..sy*4+3

    // Load Q tile transposed + pre-scaled by 1/sqrt(64)
    {
        const float* qg = g_q + ((size_t)bh*SEQ + q0)*DKDIM;
        const int c4 = tid & 15;       // float4 column in d
        const int r0 = (tid >> 4) * 8; // 8 rows per thread
        #pragma unroll
        for (int r = 0; r < 8; r++) {
            float4 v = *(const float4*)(qg + (size_t)(r0+r)*DKDIM + c4*4);
            Qt[c4*4+0][r0+r] = v.x * 0.125f;
            Qt[c4*4+1][r0+r] = v.y * 0.125f;
            Qt[c4*4+2][r0+r] = v.z * 0.125f;
            Qt[c4*4+3][r0+r] = v.w * 0.125f;
        }
    }
    if (tid < ABM) { m_row[tid] = -1e30f; l_row[tid] = 0.f; }

    float acc[4][8];
    #pragma unroll
    for (int r = 0; r < 4; r++)
        #pragma unroll
        for (int j = 0; j < 8; j++) acc[r][j] = 0.f;

    const float* kb = g_k + (size_t)bh*SEQ*DKDIM;
    const float* vb = g_v + (size_t)bh*SEQ*DKDIM;
    const int nkt = (qb + 1) * (ABM / ABN);

    for (int kt = 0; kt < nkt; kt++) {
        const int kbase = kt * ABN;
        __syncthreads();   // prev PV done before overwriting Kt/Vsh

        // Load K (transposed) and V tiles: 32 rows x 16 float4 = 512 each
        #pragma unroll
        for (int t = 0; t < 2; t++) {
            const int idx = tid + t*256;
            const int n   = idx >> 4;
            const int d4  = idx & 15;
            float4 kv = *(const float4*)(kb + (size_t)(kbase+n)*DKDIM + d4*4);
            Kt[d4*4+0][n] = kv.x; Kt[d4*4+1][n] = kv.y;
            Kt[d4*4+2][n] = kv.z; Kt[d4*4+3][n] = kv.w;
            *(float4*)&Vsh[n][d4*4] = *(const float4*)(vb + (size_t)(kbase+n)*DKDIM + d4*4);
        }
        __syncthreads();

        // --- Score GEMM: s[4][4] = Q[rows sy*4..][.] * K^T[cols sx*4..] ---
        float s[4][4];
        #pragma unroll
        for (int r = 0; r < 4; r++)
            #pragma unroll
            for (int cc = 0; cc < 4; cc++) s[r][cc] = 0.f;

        #pragma unroll 16
        for (int k = 0; k < DKDIM; k++) {
            float4 a = *(const float4*)&Qt[k][sy*4];
            float4 b = *(const float4*)&Kt[k][sx*4];
            float av[4] = {a.x, a.y, a.z, a.w};
            float bv[4] = {b.x, b.y, b.z, b.w};
            #pragma unroll
            for (int r = 0; r < 4; r++)
                #pragma unroll
                for (int cc = 0; cc < 4; cc++)
                    s[r][cc] += av[r] * bv[cc];
        }

        // --- Mask + per-row tile max (reduce over the 8 sx lanes) ---
        float rm[4];
        #pragma unroll
        for (int r = 0; r < 4; r++) {
            const int row = q0 + sy*4 + r;
            #pragma unroll
            for (int cc = 0; cc < 4; cc++)
                if (kbase + sx*4 + cc > row) s[r][cc] = -1e30f;
            rm[r] = fmaxf(fmaxf(s[r][0], s[r][1]), fmaxf(s[r][2], s[r][3]));
        }
        #pragma unroll
        for (int m = 1; m < 8; m <<= 1)
            #pragma unroll
            for (int r = 0; r < 4; r++)
                rm[r] = fmaxf(rm[r], __shfl_xor_sync(0xffffffffu, rm[r], m));

        // --- Online softmax stats (sx-group is intra-warp: lockstep safe) ---
        float newm[4], cr[4], ps[4];
        #pragma unroll
        for (int r = 0; r < 4; r++) {
            const float mo = m_row[sy*4 + r];
            newm[r] = fmaxf(mo, rm[r]);
            cr[r]   = __expf(mo - newm[r]);
        }
        #pragma unroll
        for (int r = 0; r < 4; r++) {
            float p0 = __expf(s[r][0] - newm[r]);
            float p1 = __expf(s[r][1] - newm[r]);
            float p2 = __expf(s[r][2] - newm[r]);
            float p3 = __expf(s[r][3] - newm[r]);
            Pt[sx*4+0][sy*4+r] = p0;
            Pt[sx*4+1][sy*4+r] = p1;
            Pt[sx*4+2][sy*4+r] = p2;
            Pt[sx*4+3][sy*4+r] = p3;
            ps[r] = (p0 + p1) + (p2 + p3);
        }
        #pragma unroll
        for (int m = 1; m < 8; m <<= 1)
            #pragma unroll
            for (int r = 0; r < 4; r++)
                ps[r] += __shfl_xor_sync(0xffffffffu, ps[r], m);
        if (sx == 0) {
            #pragma unroll
            for (int r = 0; r < 4; r++) {
                const int row = sy*4 + r;
                m_row[row] = newm[r];
                l_row[row] = l_row[row] * cr[r] + ps[r];
            }
        }
        __syncthreads();

        // --- Rescale acc and accumulate PV: O[sy*4..][sx*8..] += P * V ---
        #pragma unroll
        for (int r = 0; r < 4; r++)
            #pragma unroll
            for (int j = 0; j < 8; j++) acc[r][j] *= cr[r];

        #pragma unroll 8
        for (int n = 0; n < ABN; n++) {
            float4 a  = *(const float4*)&Pt[n][sy*4];
            float4 b0 = *(const float4*)&Vsh[n][sx*8];
            float4 b1 = *(const float4*)&Vsh[n][sx*8 + 4];
            float av[4] = {a.x, a.y, a.z, a.w};
            float bv[8] = {b0.x, b0.y, b0.z, b0.w, b1.x, b1.y, b1.z, b1.w};
            #pragma unroll
            for (int r = 0; r < 4; r++)
                #pragma unroll
                for (int j = 0; j < 8; j++)
                    acc[r][j] += av[r] * bv[j];
        }
    }

    // --- Epilogue: normalize and write [B,S,H*64] ---
    const int b = bh >> 4, h = bh & 15;
    #pragma unroll
    for (int r = 0; r < 4; r++) {
        const int row = sy*4 + r;
        const float inv = 1.0f / l_row[row];
        float* dst = g_attn + ((size_t)(b*SEQ + q0 + row))*DMODEL + h*DKDIM + sx*8;
        *(float4*)(dst)     = make_float4(acc[r][0]*inv, acc[r][1]*inv,
                                          acc[r][2]*inv, acc[r][3]*inv);
        *(float4*)(dst + 4) = make_float4(acc[r][4]*inv, acc[r][5]*inv,
                                          acc[r][6]*inv, acc[r][7]*inv);
    }
}

// ---------------------------------------------------------------------------
// Kernel 3: output GEMM (out = attn * Wout^T), 64x64x16 tiling.
// ---------------------------------------------------------------------------
__global__ __launch_bounds__(256)
void out_gemm_kernel(const float* __restrict__ Wout, float* __restrict__ out)
{
    __shared__ float As[BK][BM + 4];
    __shared__ float Bs[BK][BN + 4];

    const int tid  = threadIdx.x;
    const int row0 = blockIdx.x * BM;
    const int col0 = blockIdx.y * BN;
    const int tx = tid & 15;
    const int ty = tid >> 4;
    const int lr = tid >> 2;
    const int lk = (tid & 3) * 4;

    float c[4][4] = {};

    for (int k0 = 0; k0 < DMODEL; k0 += BK) {
        float4 a4 = *(const float4*)(g_attn + (size_t)(row0 + lr) * DMODEL + k0 + lk);
        float4 b4 = *(const float4*)(Wout   + (size_t)(col0 + lr) * DMODEL + k0 + lk);
        __syncthreads();
        As[lk+0][lr] = a4.x; As[lk+1][lr] = a4.y; As[lk+2][lr] = a4.z; As[lk+3][lr] = a4.w;
        Bs[lk+0][lr] = b4.x; Bs[lk+1][lr] = b4.y; Bs[lk+2][lr] = b4.z; Bs[lk+3][lr] = b4.w;
        __syncthreads();
        #pragma unroll
        for (int kk = 0; kk < BK; kk++) {
            float4 av = *(const float4*)&As[kk][ty*4];
            float4 bv = *(const float4*)&Bs[kk][tx*4];
            float a[4] = {av.x, av.y, av.z, av.w};
            float b[4] = {bv.x, bv.y, bv.z, bv.w};
            #pragma unroll
            for (int i = 0; i < 4; i++)
                #pragma unroll
                for (int j = 0; j < 4; j++)
                    c[i][j] += a[i] * b[j];
        }
    }

    #pragma unroll
    for (int i = 0; i < 4; i++) {
        const int m = row0 + ty*4 + i;
        *(float4*)(out + (size_t)m*DMODEL + col0 + tx*4) =
            make_float4(c[i][0], c[i][1], c[i][2], c[i][3]);
    }
}

// ---------------------------------------------------------------------------
extern "C" void kernel_launch(void* const* d_in, const int* in_sizes, int n_in,
                              void* d_out, int out_size)
{
    const float* x      = (const float*)d_in[0];
    const int*   tokpos = (const int*)  d_in[1];
    const float* Wqkv   = (const float*)d_in[2];
    const float* Wout   = (const float*)d_in[3];
    float*       out    = (float*)d_out;

    rope_table_kernel<<<SEQ*32/256, 256>>>(tokpos);
    qkv_gemm_kernel<<<dim3(MROWS/BM, NQKV/BN), 256>>>(x, Wqkv);
    attn_kernel<<<dim3(SEQ/ABM, BATCH*NHEADS), 256>>>();
    out_gemm_kernel<<<dim3(MROWS/BM, DMODEL/BN), 256>>>(Wout, out);
}